// round 7
// baseline (speedup 1.0000x reference)
#include <cuda_runtime.h>

// GPUBiasingMultiModel R7: single fused kernel.
//
// Block = (tile, model, hyp-chunk).
//   Phase A: compact this chunk's hyps of model m into smem; per hyp, walk
//            the <=4-hop backoff chain once, recording per-level arc-segment
//            bases + accumulated backoff weights (smem) and c_h.
//   Phase B: broadcast default fill from the start-state identity segment
//            (register-resident tile, float4 __stcs stores).
//   Phase C (after __syncthreads, which orders phase-B stores at block
//            scope): sweep the <=n*nl*K specific arcs, keep those whose
//            ilabel falls in this tile's label range, resolve first-match
//            priority, and overwrite. eos column patched by its owning tile.
//
// This removes the standalone override kernel (9.5us at 15% occupancy in R6)
// and its launch gap: the same work now runs inside 1024 well-occupied blocks
// and overlaps the store drain.

#define MAXLVL 4
#define TILE   1024   // labels per tile (8 floats/thread @128 thr)
#define CHUNK  128    // hyp indices per block (== blockDim)

__global__ void __launch_bounds__(128) fused_kernel(
    const float* __restrict__ arc_w, const int* __restrict__ arc_to,
    const int*   __restrict__ arc_ilab,
    const int*   __restrict__ model_ids, const float* __restrict__ alpha,
    const int*   __restrict__ states,
    const int*   __restrict__ bo_to, const float* __restrict__ bo_w,
    const float* __restrict__ final_w, const int* __restrict__ eos_ptr,
    float* __restrict__ out_scores, float* __restrict__ out_next,
    int V, int per_model, int B, int S, int K)
{
    const int tile = blockIdx.x;
    const int m    = blockIdx.y;
    const int h0   = blockIdx.z * CHUNK;
    const int t    = threadIdx.x;

    __shared__ int   sh_h [CHUNK];
    __shared__ float sh_c [CHUNK];
    __shared__ int   sh_s0[CHUNK];
    __shared__ int   sh_nl[CHUNK];
    __shared__ int   sh_lb[CHUNK][MAXLVL];   // per-level arc-segment base
    __shared__ float sh_la[CHUNK][MAXLVL];   // per-level accumulated backoff
    __shared__ int   sh_n;

    if (t == 0) sh_n = 0;
    __syncthreads();

    const float a = __ldg(alpha + m);

    // ---- Phase A: compact hyps + chain walk (one hyp per thread) ----
    {
        int h = h0 + t;
        if (h < B && __ldg(model_ids + h) == m) {
            int s = __ldg(states + h);
            int s_first = s;
            float acc = 0.f;
            int nl = 0;
            int   lb[MAXLVL];
            float la[MAXLVL];
            #pragma unroll
            for (int i = 0; i < MAXLVL; i++) {
                int mm = s / S, r = s - mm * S;
                if (r == 0) break;               // reached start state
                lb[nl] = mm * per_model + V + (r - 1) * K;
                la[nl] = acc;
                nl++;
                acc += __ldg(bo_w + s);
                s = __ldg(bo_to + s);
            }
            int slot = atomicAdd(&sh_n, 1);
            sh_h [slot] = h;
            sh_c [slot] = acc * a;
            sh_s0[slot] = s_first;
            sh_nl[slot] = nl;
            #pragma unroll
            for (int l = 0; l < MAXLVL; l++) { sh_lb[slot][l] = lb[l]; sh_la[slot][l] = la[l]; }
        }
    }

    // ---- Tile load (independent; overlaps phase A latency) ----
    const long long base = (long long)m * per_model + (long long)tile * TILE;
    const float4* wsrc = (const float4*)(arc_w  + base);
    const int4*   tsrc = (const int4*)  (arc_to + base);
    float4 w0 = __ldg(wsrc + t);
    float4 w1 = __ldg(wsrc + t + 128);
    int4   i0 = __ldg(tsrc + t);
    int4   i1 = __ldg(tsrc + t + 128);
    float4 n0 = make_float4((float)i0.x, (float)i0.y, (float)i0.z, (float)i0.w);
    float4 n1 = make_float4((float)i1.x, (float)i1.y, (float)i1.z, (float)i1.w);

    __syncthreads();

    // ---- Phase B: broadcast default fill ----
    const int n = sh_n;
    for (int i = 0; i < n; i++) {
        const int   h = sh_h[i];
        const float c = sh_c[i];
        float4 s0, s1;
        s0.x = fmaf(a, w0.x, c); s0.y = fmaf(a, w0.y, c);
        s0.z = fmaf(a, w0.z, c); s0.w = fmaf(a, w0.w, c);
        s1.x = fmaf(a, w1.x, c); s1.y = fmaf(a, w1.y, c);
        s1.z = fmaf(a, w1.z, c); s1.w = fmaf(a, w1.w, c);
        const long long off = (long long)h * V + (long long)tile * TILE;
        float4* sdst = (float4*)(out_scores + off);
        __stcs(sdst + t,       s0);
        __stcs(sdst + t + 128, s1);
        if (out_next) {
            float4* ndst = (float4*)(out_next + off);
            __stcs(ndst + t,       n0);
            __stcs(ndst + t + 128, n1);
        }
    }

    // Order phase-B stores before the overrides (block scope suffices: this
    // block exclusively owns the (hyp-row x label-range) region it writes).
    __syncthreads();

    // ---- Phase C: override scatter for this tile's label range ----
    const int eos = __ldg(eos_ptr);
    const int vlo = tile * TILE, vhi = vlo + TILE;

    // eos column (owned by the tile containing it)
    if (eos >= vlo && eos < vhi && t < n) {
        int h  = sh_h[t];
        int st = sh_s0[t];
        long long off = (long long)h * V + eos;
        out_scores[off] = __ldg(final_w + st) * a;
        if (out_next) out_next[off] = (float)st;
    }

    const int per_hyp = MAXLVL * K;
    const int total   = n * per_hyp;
    for (int idx = t; idx < total; idx += CHUNK) {
        const int i   = idx / per_hyp;
        const int rem = idx - i * per_hyp;
        const int l   = rem / K;
        const int j   = rem - l * K;
        if (l >= sh_nl[i]) continue;
        const int lbase = sh_lb[i][l];
        const int il = __ldg(arc_ilab + lbase + j);
        if (il < vlo || il >= vhi) continue;                          // other tile
        if (il == eos) continue;                                      // eos fixed
        if (j > 0 && __ldg(arc_ilab + lbase + j - 1) == il) continue; // leftmost wins
        bool shadowed = false;
        #pragma unroll
        for (int l2 = 0; l2 < MAXLVL - 1; l2++) {                     // earlier level wins
            if (l2 >= l) break;
            const int b2 = sh_lb[i][l2];
            int lo = 0, hi = K;
            while (lo < hi) {
                int mid = (lo + hi) >> 1;
                if (__ldg(arc_ilab + b2 + mid) < il) lo = mid + 1; else hi = mid;
            }
            if (lo < K && __ldg(arc_ilab + b2 + lo) == il) { shadowed = true; break; }
        }
        if (shadowed) continue;
        const long long off = (long long)sh_h[i] * V + il;
        out_scores[off] = (sh_la[i][l] + __ldg(arc_w + lbase + j)) * a;
        if (out_next) out_next[off] = (float)__ldg(arc_to + lbase + j);
    }
}

// ---------------- fallback: monolithic kernel (odd shapes) ----------------
#define MAXK 64
__global__ void advance_kernel(
    const float* __restrict__ arc_w, const int* __restrict__ arc_to,
    const int* __restrict__ arc_ilab,
    const int* __restrict__ bo_to, const float* __restrict__ bo_w,
    const float* __restrict__ final_w, const float* __restrict__ alpha,
    const int* __restrict__ states, const int* __restrict__ model_ids,
    const int* __restrict__ eos_ptr,
    float* __restrict__ out_scores, float* __restrict__ out_next,
    int V, int S, int K)
{
    __shared__ int       sh_ilab[MAXLVL * MAXK];
    __shared__ float     sh_w   [MAXLVL * MAXK];
    __shared__ int       sh_to  [MAXLVL * MAXK];
    __shared__ long long sh_level_base[MAXLVL];
    __shared__ float     sh_level_acc [MAXLVL];
    __shared__ int       sh_nl;
    __shared__ long long sh_start_base;
    __shared__ float     sh_start_acc;

    const int b = blockIdx.x;
    if (threadIdx.x == 0) {
        int s = states[b];
        float acc = 0.f;
        int nl = 0;
        long long start_base = -1;
        float start_acc = 0.f;
        const long long per_model = (long long)V + (long long)(S - 1) * K;
        #pragma unroll
        for (int i = 0; i < MAXLVL; i++) {
            int m = s / S, r = s - m * S;
            if (r == 0) { start_base = (long long)m * per_model; start_acc = acc; break; }
            sh_level_base[nl] = (long long)m * per_model + V + (long long)(r - 1) * K;
            sh_level_acc [nl] = acc;
            nl++;
            acc += bo_w[s];
            s = bo_to[s];
        }
        sh_nl = nl; sh_start_base = start_base; sh_start_acc = start_acc;
    }
    __syncthreads();

    const int nl = sh_nl;
    for (int idx = threadIdx.x; idx < nl * K; idx += blockDim.x) {
        int l = idx / K, j = idx - l * K;
        long long base = sh_level_base[l];
        sh_ilab[l * MAXK + j] = arc_ilab[base + j];
        sh_w   [l * MAXK + j] = arc_w   [base + j];
        sh_to  [l * MAXK + j] = arc_to  [base + j];
    }

    const int       s0      = states[b];
    const float     alpha_b = alpha[model_ids[b]];
    const int       eos     = eos_ptr[0];
    const long long sb      = sh_start_base;
    const float     sa      = sh_start_acc;
    const float     eos_sc  = final_w[s0] * alpha_b;
    const long long off     = (long long)b * V;

    for (int v = threadIdx.x; v < V; v += blockDim.x) {
        float sc = 0.f, nx = 0.f;
        if (sb >= 0) {
            sc = (sa + arc_w[sb + v]) * alpha_b;
            nx = (float)arc_to[sb + v];
        }
        if (v == eos) { sc = eos_sc; nx = (float)s0; }
        out_scores[off + v] = sc;
        if (out_next) out_next[off + v] = nx;
    }
    __syncthreads();

    for (int idx = threadIdx.x; idx < nl * K; idx += blockDim.x) {
        int l = idx / K, j = idx - l * K;
        int il = sh_ilab[l * MAXK + j];
        if (il == eos) continue;
        if (j > 0 && sh_ilab[l * MAXK + j - 1] == il) continue;
        bool shadowed = false;
        for (int l2 = 0; l2 < l; l2++) {
            const int* arr = sh_ilab + l2 * MAXK;
            int lo = 0, hi = K;
            while (lo < hi) { int mid = (lo + hi) >> 1; if (arr[mid] < il) lo = mid + 1; else hi = mid; }
            if (lo < K && arr[lo] == il) { shadowed = true; break; }
        }
        if (shadowed) continue;
        out_scores[off + il] = (sh_level_acc[l] + sh_w[l * MAXK + j]) * alpha_b;
        if (out_next) out_next[off + il] = (float)sh_to[l * MAXK + j];
    }
}

extern "C" void kernel_launch(void* const* d_in, const int* in_sizes, int n_in,
                              void* d_out, int out_size)
{
    const float* arc_w     = (const float*)d_in[0];
    const int*   arc_to    = (const int*)  d_in[1];
    const int*   arc_ilab  = (const int*)  d_in[3];
    const int*   bo_to     = (const int*)  d_in[4];
    const float* bo_w      = (const float*)d_in[5];
    const float* final_w   = (const float*)d_in[6];
    const float* alpha     = (const float*)d_in[7];
    const int*   states    = (const int*)  d_in[8];
    const int*   model_ids = (const int*)  d_in[9];
    const int*   eos       = (const int*)  d_in[10];

    const long long A        = in_sizes[0];
    const long long n_states = in_sizes[4];
    const long long M        = in_sizes[7];
    const long long B        = in_sizes[8];
    const long long S        = n_states / M;

    long long V = (long long)out_size / (2 * B);
    bool write_next = true;
    if (V * 2 * B != (long long)out_size) {
        V = (long long)out_size / B;
        write_next = false;
    }
    const long long per_model = A / M;
    const int K = (int)((per_model - V) / (S - 1));

    float* out_scores = (float*)d_out;
    float* out_next   = write_next ? out_scores + B * V : nullptr;

    if ((V % TILE) == 0) {
        dim3 grid((unsigned)(V / TILE), (unsigned)M, (unsigned)((B + CHUNK - 1) / CHUNK));
        fused_kernel<<<grid, CHUNK>>>(
            arc_w, arc_to, arc_ilab, model_ids, alpha, states, bo_to, bo_w,
            final_w, eos,
            out_scores, out_next, (int)V, (int)per_model, (int)B, (int)S, K);
    } else {
        advance_kernel<<<(unsigned)B, 256>>>(
            arc_w, arc_to, arc_ilab, bo_to, bo_w, final_w, alpha,
            states, model_ids, eos,
            out_scores, out_next, (int)V, (int)S, K);
    }
}

// round 8
// speedup vs baseline: 1.4401x; 1.4401x over previous
#include <cuda_runtime.h>

// GPUBiasingMultiModel R8: two kernels, chain info precomputed in KB.
//
//  KB (unchanged structure from R6 -- proven at the ~5.1TB/s store floor):
//      broadcast default fill; Block=(tile,model,chunk); chunk hyps compacted
//      into smem with inline backoff-chain walk; float4 __stcs stores.
//      NEW: tile==0 blocks persist each hyp's chain record (nl, level bases,
//      level accs) into __device__ scratch for KC.
//  KC: warp-per-hyp override scatter. Chain record comes from scratch
//      (depth-2 load chain instead of the ~7-deep walk that made every prior
//      KC shape cost 8-9.5us). K==32 fast path: arcs live one-per-lane;
//      leftmost-dup via shfl_up, shadow check via 5-step shuffle binary
//      search over the earlier level's lane-resident sorted ilabels.

#define MAXLVL 4
#define MAXB   4096
#define TILE   1024   // labels per tile (8 floats/thread @128 thr)
#define CHUNK  128    // hyp indices per block (== blockDim)

__device__ int   g_nl[MAXB];
__device__ int   g_lb[MAXB][MAXLVL];
__device__ float g_la[MAXB][MAXLVL];

// ---------------- KB: broadcast default fill ----------------
__global__ void __launch_bounds__(128) broadcast_kernel(
    const float* __restrict__ arc_w, const int* __restrict__ arc_to,
    const int* __restrict__ model_ids, const float* __restrict__ alpha,
    const int* __restrict__ states,
    const int* __restrict__ bo_to, const float* __restrict__ bo_w,
    float* __restrict__ out_scores, float* __restrict__ out_next,
    int V, int per_model, int B, int S, int K)
{
    const int tile = blockIdx.x;
    const int m    = blockIdx.y;
    const int h0   = blockIdx.z * CHUNK;
    const int t    = threadIdx.x;

    __shared__ int   sh_h[CHUNK];
    __shared__ float sh_c[CHUNK];
    __shared__ int   sh_n;

    if (t == 0) sh_n = 0;
    __syncthreads();

    const float a = __ldg(alpha + m);

    // Phase A: compact this chunk's hyps of model m; walk the chain once.
    {
        int h = h0 + t;
        if (h < B && __ldg(model_ids + h) == m) {
            int s = __ldg(states + h);
            float acc = 0.f;
            int nl = 0;
            int   lb[MAXLVL] = {0, 0, 0, 0};
            float la[MAXLVL] = {0.f, 0.f, 0.f, 0.f};
            #pragma unroll
            for (int i = 0; i < MAXLVL; i++) {
                int mm = s / S, r = s - mm * S;
                if (r == 0) break;              // reached start state
                lb[nl] = mm * per_model + V + (r - 1) * K;
                la[nl] = acc;
                nl++;
                acc += __ldg(bo_w + s);
                s = __ldg(bo_to + s);
            }
            int slot = atomicAdd(&sh_n, 1);
            sh_h[slot] = h;
            sh_c[slot] = acc * a;
            if (tile == 0) {                    // persist chain record for KC
                g_nl[h] = nl;
                #pragma unroll
                for (int l = 0; l < MAXLVL; l++) { g_lb[h][l] = lb[l]; g_la[h][l] = la[l]; }
            }
        }
    }

    // Tile load (independent; overlaps phase A latency).
    const long long base = (long long)m * per_model + (long long)tile * TILE;
    const float4* wsrc = (const float4*)(arc_w  + base);
    const int4*   tsrc = (const int4*)  (arc_to + base);
    float4 w0 = __ldg(wsrc + t);
    float4 w1 = __ldg(wsrc + t + 128);
    int4   i0 = __ldg(tsrc + t);
    int4   i1 = __ldg(tsrc + t + 128);
    float4 n0 = make_float4((float)i0.x, (float)i0.y, (float)i0.z, (float)i0.w);
    float4 n1 = make_float4((float)i1.x, (float)i1.y, (float)i1.z, (float)i1.w);

    __syncthreads();

    const int n = sh_n;
    for (int i = 0; i < n; i++) {
        const int   h = sh_h[i];
        const float c = sh_c[i];
        float4 s0, s1;
        s0.x = fmaf(a, w0.x, c); s0.y = fmaf(a, w0.y, c);
        s0.z = fmaf(a, w0.z, c); s0.w = fmaf(a, w0.w, c);
        s1.x = fmaf(a, w1.x, c); s1.y = fmaf(a, w1.y, c);
        s1.z = fmaf(a, w1.z, c); s1.w = fmaf(a, w1.w, c);
        const long long off = (long long)h * V + (long long)tile * TILE;
        float4* sdst = (float4*)(out_scores + off);
        __stcs(sdst + t,       s0);
        __stcs(sdst + t + 128, s1);
        if (out_next) {
            float4* ndst = (float4*)(out_next + off);
            __stcs(ndst + t,       n0);
            __stcs(ndst + t + 128, n1);
        }
    }
}

// ---------------- KC: warp-per-hyp overrides + eos ----------------
__global__ void __launch_bounds__(128) override_kernel(
    const float* __restrict__ arc_w, const int* __restrict__ arc_to,
    const int* __restrict__ arc_ilab,
    const float* __restrict__ final_w, const float* __restrict__ alpha,
    const int* __restrict__ states, const int* __restrict__ model_ids,
    const int* __restrict__ eos_ptr,
    float* __restrict__ out_scores, float* __restrict__ out_next,
    int V, int K, int B)
{
    const int lane = threadIdx.x & 31;
    const int b    = blockIdx.x * 4 + (threadIdx.x >> 5);
    if (b >= B) return;

    const float alpha_b = __ldg(alpha + __ldg(model_ids + b));
    const int   eos     = __ldg(eos_ptr);
    const long long out_off = (long long)b * V;

    if (lane == 0) {     // eos column: final weight, stay in place
        int s0 = __ldg(states + b);
        out_scores[out_off + eos] = __ldg(final_w + s0) * alpha_b;
        if (out_next) out_next[out_off + eos] = (float)s0;
    }

    const int nl = g_nl[b];      // uniform per warp
    if (nl == 0) return;

    if (K == 32) {
        // Fast path: arc j of each level lives in lane j.
        int   bases[MAXLVL];
        float accs [MAXLVL];
        int   il   [MAXLVL];
        #pragma unroll
        for (int l = 0; l < MAXLVL; l++) {
            if (l < nl) {
                bases[l] = g_lb[b][l];
                accs [l] = g_la[b][l];
                il   [l] = __ldg(arc_ilab + bases[l] + lane);
            }
        }
        #pragma unroll
        for (int l = 0; l < MAXLVL; l++) {
            if (l >= nl) break;
            const int x = il[l];
            bool write = (x != eos);
            int prev = __shfl_up_sync(0xffffffffu, x, 1);
            if (lane > 0 && prev == x) write = false;       // leftmost wins
            #pragma unroll
            for (int l2 = 0; l2 < MAXLVL - 1; l2++) {       // earlier level wins
                if (l2 >= l) break;
                const int arr = il[l2];                      // sorted across lanes
                int lo = 0, hi = 32;
                #pragma unroll
                for (int it = 0; it < 5; it++) {             // shuffle lower_bound
                    int mid = (lo + hi) >> 1;
                    int v = __shfl_sync(0xffffffffu, arr, mid);
                    if (v < x) lo = mid + 1; else hi = mid;
                }
                int vlo = __shfl_sync(0xffffffffu, arr, lo < 32 ? lo : 0);
                if (lo < 32 && vlo == x) write = false;
            }
            if (write) {
                out_scores[out_off + x] = (accs[l] + __ldg(arc_w + bases[l] + lane)) * alpha_b;
                if (out_next) out_next[out_off + x] = (float)__ldg(arc_to + bases[l] + lane);
            }
        }
    } else {
        // Generic path: memory binary search for shadow checks.
        #pragma unroll
        for (int l = 0; l < MAXLVL; l++) {
            if (l >= nl) break;
            const int lbase = g_lb[b][l];
            for (int j = lane; j < K; j += 32) {
                const int x = __ldg(arc_ilab + lbase + j);
                if (x == eos) continue;
                if (j > 0 && __ldg(arc_ilab + lbase + j - 1) == x) continue;
                bool shadowed = false;
                #pragma unroll
                for (int l2 = 0; l2 < MAXLVL - 1; l2++) {
                    if (l2 >= l) break;
                    const int b2 = g_lb[b][l2];
                    int lo = 0, hi = K;
                    while (lo < hi) {
                        int mid = (lo + hi) >> 1;
                        if (__ldg(arc_ilab + b2 + mid) < x) lo = mid + 1; else hi = mid;
                    }
                    if (lo < K && __ldg(arc_ilab + b2 + lo) == x) { shadowed = true; break; }
                }
                if (shadowed) continue;
                out_scores[out_off + x] = (g_la[b][l] + __ldg(arc_w + lbase + j)) * alpha_b;
                if (out_next) out_next[out_off + x] = (float)__ldg(arc_to + lbase + j);
            }
        }
    }
}

// ---------------- fallback: monolithic kernel (odd shapes) ----------------
#define MAXK 64
__global__ void advance_kernel(
    const float* __restrict__ arc_w, const int* __restrict__ arc_to,
    const int* __restrict__ arc_ilab,
    const int* __restrict__ bo_to, const float* __restrict__ bo_w,
    const float* __restrict__ final_w, const float* __restrict__ alpha,
    const int* __restrict__ states, const int* __restrict__ model_ids,
    const int* __restrict__ eos_ptr,
    float* __restrict__ out_scores, float* __restrict__ out_next,
    int V, int S, int K)
{
    __shared__ int       sh_ilab[MAXLVL * MAXK];
    __shared__ float     sh_w   [MAXLVL * MAXK];
    __shared__ int       sh_to  [MAXLVL * MAXK];
    __shared__ long long sh_level_base[MAXLVL];
    __shared__ float     sh_level_acc [MAXLVL];
    __shared__ int       sh_nl;
    __shared__ long long sh_start_base;
    __shared__ float     sh_start_acc;

    const int b = blockIdx.x;
    if (threadIdx.x == 0) {
        int s = states[b];
        float acc = 0.f;
        int nl = 0;
        long long start_base = -1;
        float start_acc = 0.f;
        const long long per_model = (long long)V + (long long)(S - 1) * K;
        #pragma unroll
        for (int i = 0; i < MAXLVL; i++) {
            int m = s / S, r = s - m * S;
            if (r == 0) { start_base = (long long)m * per_model; start_acc = acc; break; }
            sh_level_base[nl] = (long long)m * per_model + V + (long long)(r - 1) * K;
            sh_level_acc [nl] = acc;
            nl++;
            acc += bo_w[s];
            s = bo_to[s];
        }
        sh_nl = nl; sh_start_base = start_base; sh_start_acc = start_acc;
    }
    __syncthreads();

    const int nl = sh_nl;
    for (int idx = threadIdx.x; idx < nl * K; idx += blockDim.x) {
        int l = idx / K, j = idx - l * K;
        long long base = sh_level_base[l];
        sh_ilab[l * MAXK + j] = arc_ilab[base + j];
        sh_w   [l * MAXK + j] = arc_w   [base + j];
        sh_to  [l * MAXK + j] = arc_to  [base + j];
    }

    const int       s0      = states[b];
    const float     alpha_b = alpha[model_ids[b]];
    const int       eos     = eos_ptr[0];
    const long long sb      = sh_start_base;
    const float     sa      = sh_start_acc;
    const float     eos_sc  = final_w[s0] * alpha_b;
    const long long off     = (long long)b * V;

    for (int v = threadIdx.x; v < V; v += blockDim.x) {
        float sc = 0.f, nx = 0.f;
        if (sb >= 0) {
            sc = (sa + arc_w[sb + v]) * alpha_b;
            nx = (float)arc_to[sb + v];
        }
        if (v == eos) { sc = eos_sc; nx = (float)s0; }
        out_scores[off + v] = sc;
        if (out_next) out_next[off + v] = nx;
    }
    __syncthreads();

    for (int idx = threadIdx.x; idx < nl * K; idx += blockDim.x) {
        int l = idx / K, j = idx - l * K;
        int il = sh_ilab[l * MAXK + j];
        if (il == eos) continue;
        if (j > 0 && sh_ilab[l * MAXK + j - 1] == il) continue;
        bool shadowed = false;
        for (int l2 = 0; l2 < l; l2++) {
            const int* arr = sh_ilab + l2 * MAXK;
            int lo = 0, hi = K;
            while (lo < hi) { int mid = (lo + hi) >> 1; if (arr[mid] < il) lo = mid + 1; else hi = mid; }
            if (lo < K && arr[lo] == il) { shadowed = true; break; }
        }
        if (shadowed) continue;
        out_scores[off + il] = (sh_level_acc[l] + sh_w[l * MAXK + j]) * alpha_b;
        if (out_next) out_next[off + il] = (float)sh_to[l * MAXK + j];
    }
}

extern "C" void kernel_launch(void* const* d_in, const int* in_sizes, int n_in,
                              void* d_out, int out_size)
{
    const float* arc_w     = (const float*)d_in[0];
    const int*   arc_to    = (const int*)  d_in[1];
    const int*   arc_ilab  = (const int*)  d_in[3];
    const int*   bo_to     = (const int*)  d_in[4];
    const float* bo_w      = (const float*)d_in[5];
    const float* final_w   = (const float*)d_in[6];
    const float* alpha     = (const float*)d_in[7];
    const int*   states    = (const int*)  d_in[8];
    const int*   model_ids = (const int*)  d_in[9];
    const int*   eos       = (const int*)  d_in[10];

    const long long A        = in_sizes[0];
    const long long n_states = in_sizes[4];
    const long long M        = in_sizes[7];
    const long long B        = in_sizes[8];
    const long long S        = n_states / M;

    long long V = (long long)out_size / (2 * B);
    bool write_next = true;
    if (V * 2 * B != (long long)out_size) {
        V = (long long)out_size / B;
        write_next = false;
    }
    const long long per_model = A / M;
    const int K = (int)((per_model - V) / (S - 1));

    float* out_scores = (float*)d_out;
    float* out_next   = write_next ? out_scores + B * V : nullptr;

    if ((V % TILE) == 0 && B <= MAXB) {
        dim3 grid((unsigned)(V / TILE), (unsigned)M, (unsigned)((B + CHUNK - 1) / CHUNK));
        broadcast_kernel<<<grid, CHUNK>>>(
            arc_w, arc_to, model_ids, alpha, states, bo_to, bo_w,
            out_scores, out_next, (int)V, (int)per_model, (int)B, (int)S, K);
        override_kernel<<<(unsigned)((B + 3) / 4), 128>>>(
            arc_w, arc_to, arc_ilab, final_w, alpha, states, model_ids, eos,
            out_scores, out_next, (int)V, K, (int)B);
    } else {
        advance_kernel<<<(unsigned)B, 256>>>(
            arc_w, arc_to, arc_ilab, bo_to, bo_w, final_w, alpha,
            states, model_ids, eos,
            out_scores, out_next, (int)V, (int)S, K);
    }
}